// round 3
// baseline (speedup 1.0000x reference)
#include <cuda_runtime.h>
#include <math.h>

#define BB 64      // batch
#define TT 512     // seq len
#define DD 512     // input size
#define HH 1024    // hidden
#define G4 4096    // 4*HH
#define NBLK 128   // persistent blocks (must all be co-resident; 148 SMs)

// ---------------- scratch (static __device__, no allocs) ----------------
__device__ float g_G[(size_t)TT * BB * G4];      // precomputed x@W+b, rows = (t,B)
__device__ float g_hseq[(size_t)TT * BB * HH];   // layer-0 hidden sequence (T,B,H)
__device__ float g_Up0[(size_t)HH * G4];         // U0 permuted to (k, u, gate)
__device__ float g_Up1[(size_t)HH * G4];         // U1 permuted
__device__ float g_hping[2 * BB * HH];           // h ping-pong
__device__ float g_c[BB * HH];                   // cell state

// ---------------- software grid barrier (graph-replay safe: monotonic gen) --
__device__ unsigned g_cnt = 0;
__device__ volatile unsigned g_gen = 0;

__device__ __forceinline__ void grid_barrier() {
    __syncthreads();
    if (threadIdx.x == 0) {
        __threadfence();
        unsigned old = g_gen;
        if (atomicAdd(&g_cnt, 1) == NBLK - 1) {
            g_cnt = 0;
            __threadfence();
            g_gen = old + 1;
        } else {
            while (g_gen == old) { }
        }
        __threadfence();
    }
    __syncthreads();
}

__device__ __forceinline__ float d_sigmoid(float x) { return 1.0f / (1.0f + expf(-x)); }
__device__ __forceinline__ float d_tanh(float x)    { return 1.0f - 2.0f / (expf(2.0f * x) + 1.0f); }

// ---------------- U permute: Up[(k*HH + u)*4 + g] = U[k*4H + g*H + u] -------
__global__ void permuteU(const float* __restrict__ U, float* __restrict__ Up) {
    int idx = blockIdx.x * blockDim.x + threadIdx.x;   // over HH*HH
    if (idx >= HH * HH) return;
    int k = idx >> 10;
    int u = idx & (HH - 1);
    const float* src = U + (size_t)k * G4 + u;
    float4 v = make_float4(src[0], src[HH], src[2 * HH], src[3 * HH]);
    ((float4*)Up)[idx] = v;
}

// ---------------- batch GEMM: C[m][n] = A[rowmap(m)][:] @ W[:, n] + bias[n] --
// mode 0: rowmap(m) = (m % B)*T + (m / B)  (input_seq is (B,T,D), G rows are (T,B))
// mode 1: rowmap(m) = m                    (hseq already stored (T,B,H))
#define GBM 128
#define GBN 64
#define GBK 16
#define AS_STRIDE 132

__global__ __launch_bounds__(256) void gemm_xw(
    const float* __restrict__ A, const float* __restrict__ W,
    const float* __restrict__ bias, float* __restrict__ C,
    int K, int mode)
{
    __shared__ float As[GBK * AS_STRIDE];
    __shared__ float Bs[GBK * GBN];

    int tid = threadIdx.x;
    int m0 = blockIdx.y * GBM;
    int n0 = blockIdx.x * GBN;
    int ty = tid >> 4;
    int tx = tid & 15;

    float acc[8][4];
#pragma unroll
    for (int i = 0; i < 8; i++)
#pragma unroll
        for (int j = 0; j < 4; j++) acc[i][j] = 0.0f;

    int am = tid >> 2;
    int ak = (tid & 3) * 4;
    int mA0 = m0 + am;
    int mA1 = m0 + am + 64;
    size_t arow0 = (mode == 0) ? (size_t)(mA0 & 63) * TT + (mA0 >> 6) : (size_t)mA0;
    size_t arow1 = (mode == 0) ? (size_t)(mA1 & 63) * TT + (mA1 >> 6) : (size_t)mA1;

    int bk = tid >> 4;
    int bn = (tid & 15) * 4;

    for (int kc = 0; kc < K; kc += GBK) {
        float4 va0 = *(const float4*)&A[arow0 * K + kc + ak];
        float4 va1 = *(const float4*)&A[arow1 * K + kc + ak];
        As[(ak + 0) * AS_STRIDE + am] = va0.x;
        As[(ak + 1) * AS_STRIDE + am] = va0.y;
        As[(ak + 2) * AS_STRIDE + am] = va0.z;
        As[(ak + 3) * AS_STRIDE + am] = va0.w;
        As[(ak + 0) * AS_STRIDE + am + 64] = va1.x;
        As[(ak + 1) * AS_STRIDE + am + 64] = va1.y;
        As[(ak + 2) * AS_STRIDE + am + 64] = va1.z;
        As[(ak + 3) * AS_STRIDE + am + 64] = va1.w;

        float4 vb = *(const float4*)&W[(size_t)(kc + bk) * G4 + n0 + bn];
        *(float4*)&Bs[bk * GBN + bn] = vb;

        __syncthreads();
#pragma unroll
        for (int kk = 0; kk < GBK; kk++) {
            float4 a0 = *(const float4*)&As[kk * AS_STRIDE + ty * 8];
            float4 a1 = *(const float4*)&As[kk * AS_STRIDE + ty * 8 + 4];
            float4 bv = *(const float4*)&Bs[kk * GBN + tx * 4];
            float av[8] = {a0.x, a0.y, a0.z, a0.w, a1.x, a1.y, a1.z, a1.w};
#pragma unroll
            for (int i = 0; i < 8; i++) {
                acc[i][0] += av[i] * bv.x;
                acc[i][1] += av[i] * bv.y;
                acc[i][2] += av[i] * bv.z;
                acc[i][3] += av[i] * bv.w;
            }
        }
        __syncthreads();
    }

    float4 bias4 = *(const float4*)&bias[n0 + tx * 4];
#pragma unroll
    for (int i = 0; i < 8; i++) {
        float4 r;
        r.x = acc[i][0] + bias4.x;
        r.y = acc[i][1] + bias4.y;
        r.z = acc[i][2] + bias4.z;
        r.w = acc[i][3] + bias4.w;
        *(float4*)&C[(size_t)(m0 + ty * 8 + i) * G4 + n0 + tx * 4] = r;
    }
}

// ---------------- persistent recurrent layer ----------------
// NBLK blocks x 256 threads. Block owns 8 hidden units (32 gate columns).
// Thread: unit ju = tid&7, batch pair b0 = 2*(tid>>3). Loops all T steps with a
// grid barrier between steps; h state ping-pongs in global, c owned per-thread.
#define HS_STRIDE 66

__global__ __launch_bounds__(256) void lstm_layer(
    const float* __restrict__ Gbase,  // (T, B, 4H) pre-activations
    const float* __restrict__ Up,     // permuted U: (H, H, 4)
    const float* __restrict__ h0,     // (B,H) initial h for this layer
    const float* __restrict__ c0,     // (B,H) initial c for this layer
    float* __restrict__ hbuf,         // 2*(B,H) ping-pong
    float* __restrict__ cbuf,         // (B,H)
    float* __restrict__ seq_out,      // h_t written at seq_out[t*t_str + b*b_str + u]
    int t_str, int b_str,
    float* hT, float* cT)             // optional final-state sinks
{
    __shared__ float hs[128 * HS_STRIDE];
    int tid = threadIdx.x;
    int ju = tid & 7;
    int bg = tid >> 3;
    int b0 = bg * 2;
    int u  = blockIdx.x * 8 + ju;

    // init: copy h0 -> hbuf[0], c0 -> cbuf (grid-strided)
    for (int i = blockIdx.x * 256 + tid; i < BB * HH; i += NBLK * 256) {
        hbuf[i] = h0[i];
        cbuf[i] = c0[i];
    }

    const float4* UpV = (const float4*)Up + u;   // element k lives at UpV[k*HH]

    for (int t = 0; t < TT; t++) {
        grid_barrier();   // h writes from step t-1 (or init) visible everywhere

        const float* Grow = Gbase + (size_t)t * BB * G4;
        const float* h_in = hbuf + (size_t)(t & 1) * BB * HH;
        float* h_out      = hbuf + (size_t)((t + 1) & 1) * BB * HH;

        float a00, a01, a02, a03, a10, a11, a12, a13;
        a00 = Grow[(size_t)b0 * G4 + 0 * HH + u];
        a01 = Grow[(size_t)b0 * G4 + 1 * HH + u];
        a02 = Grow[(size_t)b0 * G4 + 2 * HH + u];
        a03 = Grow[(size_t)b0 * G4 + 3 * HH + u];
        a10 = Grow[(size_t)(b0 + 1) * G4 + 0 * HH + u];
        a11 = Grow[(size_t)(b0 + 1) * G4 + 1 * HH + u];
        a12 = Grow[(size_t)(b0 + 1) * G4 + 2 * HH + u];
        a13 = Grow[(size_t)(b0 + 1) * G4 + 3 * HH + u];

        for (int kc = 0; kc < HH; kc += 128) {
            // stage h chunk transposed: hs[kk*HS_STRIDE + b]
#pragma unroll
            for (int i = 0; i < 8; i++) {
                int lid = tid + i * 256;     // 0..2047
                int b = lid >> 5;
                int k = lid & 31;
#pragma unroll
                for (int j = 0; j < 4; j++)
                    hs[(k + 32 * j) * HS_STRIDE + b] = h_in[(size_t)b * HH + kc + k + 32 * j];
            }
            __syncthreads();
#pragma unroll 8
            for (int kk = 0; kk < 128; kk++) {
                float2 h01 = *(const float2*)&hs[kk * HS_STRIDE + b0];
                float4 u4 = UpV[(size_t)(kc + kk) * HH];
                a00 += h01.x * u4.x;  a10 += h01.y * u4.x;
                a01 += h01.x * u4.y;  a11 += h01.y * u4.y;
                a02 += h01.x * u4.z;  a12 += h01.y * u4.z;
                a03 += h01.x * u4.w;  a13 += h01.y * u4.w;
            }
            __syncthreads();
        }

        bool last = (t == TT - 1);
#pragma unroll
        for (int p = 0; p < 2; p++) {
            float gi = p ? a10 : a00;
            float gf = p ? a11 : a01;
            float gg = p ? a12 : a02;
            float go = p ? a13 : a03;
            int b = b0 + p;
            int ci = b * HH + u;
            float ig = d_sigmoid(gi);
            float fg = d_sigmoid(gf);
            float gv = d_tanh(gg);
            float og = d_sigmoid(go);
            float cn = fg * cbuf[ci] + ig * gv;
            float hn = og * d_tanh(cn);
            cbuf[ci] = cn;
            h_out[ci] = hn;
            seq_out[(size_t)t * t_str + (size_t)b * b_str + u] = hn;
            if (last && hT) { hT[ci] = hn; cT[ci] = cn; }
        }
    }
}

// ---------------- launch ----------------
extern "C" void kernel_launch(void* const* d_in, const int* in_sizes, int n_in,
                              void* d_out, int out_size)
{
    const float* X  = (const float*)d_in[0];
    const float* h0 = (const float*)d_in[1];
    const float* c0 = (const float*)d_in[2];
    const float* W0 = (const float*)d_in[3];
    const float* U0 = (const float*)d_in[4];
    const float* b0 = (const float*)d_in[5];
    const float* W1 = (const float*)d_in[6];
    const float* U1 = (const float*)d_in[7];
    const float* b1 = (const float*)d_in[8];
    float* out = (float*)d_out;

    float *G, *hseq, *Up0, *Up1, *hping, *cb;
    cudaGetSymbolAddress((void**)&G,     g_G);
    cudaGetSymbolAddress((void**)&hseq,  g_hseq);
    cudaGetSymbolAddress((void**)&Up0,   g_Up0);
    cudaGetSymbolAddress((void**)&Up1,   g_Up1);
    cudaGetSymbolAddress((void**)&hping, g_hping);
    cudaGetSymbolAddress((void**)&cb,    g_c);

    // permute U0, U1 into (k, u, gate)
    permuteU<<<(HH * HH) / 256, 256>>>(U0, Up0);
    permuteU<<<(HH * HH) / 256, 256>>>(U1, Up1);

    dim3 ggrid(G4 / GBN, (TT * BB) / GBM);   // (64, 256)

    bool wantHC = (size_t)out_size >= (size_t)BB * TT * HH + 2ull * BB * HH;
    float* hT = wantHC ? out + (size_t)BB * TT * HH : nullptr;
    float* cT = wantHC ? hT + (size_t)BB * HH : nullptr;

    // ---- layer 0 ----
    gemm_xw<<<ggrid, 256>>>(X, W0, b0, G, DD, 0);
    lstm_layer<<<NBLK, 256>>>(G, Up0, h0, c0, hping, cb,
                              hseq, BB * HH, HH,       // hseq[t*B*H + b*H + u]
                              nullptr, nullptr);

    // ---- layer 1 ----
    gemm_xw<<<ggrid, 256>>>(hseq, W1, b1, G, HH, 1);
    lstm_layer<<<NBLK, 256>>>(G, Up1, h0 + (size_t)BB * HH, c0 + (size_t)BB * HH,
                              hping, cb,
                              out, HH, TT * HH,        // out[b*T*H + t*H + u]
                              hT, cT);
}